// round 2
// baseline (speedup 1.0000x reference)
#include <cuda_runtime.h>
#include <cuda_bf16.h>

// DistMult: C[i,j] = sum_k (A[i,k] * w_r[k]) * B[j,k] + bias
// A = input1 [N1, D], B = input2 [N2, D], w_r = weight[type_index], D = 512.
// Round 1: fp32 register-blocked SGEMM baseline. 128x128 block tile, BK=8,
// 256 threads, 8x8 micro-tile. w_r folded into the A shared-store.

#define DM_D  512
#define DM_BM 128
#define DM_BN 128
#define DM_BK 8

__global__ __launch_bounds__(256, 2)
void distmult_sgemm_kernel(const float* __restrict__ A,
                           const float* __restrict__ B,
                           const float* __restrict__ W,
                           const float* __restrict__ bias,
                           const int*   __restrict__ type_index,
                           float* __restrict__ C,
                           int N1, int N2) {
    __shared__ float sA[DM_BK][DM_BM];   // k-major, scaled by w_r
    __shared__ float sB[DM_BK][DM_BN];   // k-major
    __shared__ float sW[DM_D];

    const int tid = threadIdx.x;
    const int tx  = tid & 15;    // 0..15  -> N micro-tile
    const int ty  = tid >> 4;    // 0..15  -> M micro-tile

    // Cache w_r in shared once.
    const float* wr = W + (size_t)type_index[0] * DM_D;
    for (int i = tid; i < DM_D; i += 256) sW[i] = wr[i];

    const int row0 = blockIdx.y * DM_BM;
    const int col0 = blockIdx.x * DM_BN;

    // Tile-load mapping: each thread loads one float4 of A and one of B.
    const int lrow = tid >> 1;          // 0..127
    const int lk   = (tid & 1) * 4;     // 0 or 4

    const float* Aptr = A + (size_t)(row0 + lrow) * DM_D + lk;
    const float* Bptr = B + (size_t)(col0 + lrow) * DM_D + lk;

    float acc[8][8];
    #pragma unroll
    for (int i = 0; i < 8; i++)
        #pragma unroll
        for (int j = 0; j < 8; j++)
            acc[i][j] = 0.0f;

    __syncthreads();   // sW visible

    for (int k0 = 0; k0 < DM_D; k0 += DM_BK) {
        const float4 a = *(const float4*)(Aptr + k0);
        const float4 b = *(const float4*)(Bptr + k0);

        // Fold w_r into A while transposing into shared.
        sA[lk + 0][lrow] = a.x * sW[k0 + lk + 0];
        sA[lk + 1][lrow] = a.y * sW[k0 + lk + 1];
        sA[lk + 2][lrow] = a.z * sW[k0 + lk + 2];
        sA[lk + 3][lrow] = a.w * sW[k0 + lk + 3];

        sB[lk + 0][lrow] = b.x;
        sB[lk + 1][lrow] = b.y;
        sB[lk + 2][lrow] = b.z;
        sB[lk + 3][lrow] = b.w;

        __syncthreads();

        #pragma unroll
        for (int kk = 0; kk < DM_BK; kk++) {
            // A fragment: 8 consecutive rows (warp-broadcast LDS.128)
            const float4 a0 = *(const float4*)&sA[kk][ty * 8];
            const float4 a1 = *(const float4*)&sA[kk][ty * 8 + 4];
            // B fragment: split columns tx*4 and 64+tx*4 (conflict-free LDS.128)
            const float4 b0 = *(const float4*)&sB[kk][tx * 4];
            const float4 b1 = *(const float4*)&sB[kk][64 + tx * 4];

            const float ar[8] = {a0.x, a0.y, a0.z, a0.w, a1.x, a1.y, a1.z, a1.w};
            const float br[8] = {b0.x, b0.y, b0.z, b0.w, b1.x, b1.y, b1.z, b1.w};

            #pragma unroll
            for (int i = 0; i < 8; i++)
                #pragma unroll
                for (int j = 0; j < 8; j++)
                    acc[i][j] = fmaf(ar[i], br[j], acc[i][j]);
        }

        __syncthreads();
    }

    const float bv = bias[0];

    #pragma unroll
    for (int i = 0; i < 8; i++) {
        const size_t r = (size_t)(row0 + ty * 8 + i);
        float* crow = C + r * (size_t)N2 + col0;

        float4 o0, o1;
        o0.x = acc[i][0] + bv; o0.y = acc[i][1] + bv;
        o0.z = acc[i][2] + bv; o0.w = acc[i][3] + bv;
        o1.x = acc[i][4] + bv; o1.y = acc[i][5] + bv;
        o1.z = acc[i][6] + bv; o1.w = acc[i][7] + bv;

        *(float4*)(crow + tx * 4)      = o0;
        *(float4*)(crow + 64 + tx * 4) = o1;
    }
}

extern "C" void kernel_launch(void* const* d_in, const int* in_sizes, int n_in,
                              void* d_out, int out_size) {
    const float* input1     = (const float*)d_in[0];   // [N1, 512]
    const float* input2     = (const float*)d_in[1];   // [N2, 512]
    const float* weight     = (const float*)d_in[2];   // [64, 512]
    const float* bias       = (const float*)d_in[3];   // [1]
    const int*   type_index = (const int*)  d_in[4];   // [1]
    float*       out        = (float*)d_out;           // [N1, N2]

    const int N1 = in_sizes[0] / DM_D;
    const int N2 = in_sizes[1] / DM_D;

    dim3 grid(N2 / DM_BN, N1 / DM_BM);
    distmult_sgemm_kernel<<<grid, 256>>>(input1, input2, weight, bias,
                                         type_index, out, N1, N2);
}

// round 6
// speedup vs baseline: 2.1892x; 2.1892x over previous
#include <cuda_runtime.h>
#include <cuda_bf16.h>
#include <cstdint>

// DistMult: C[i,j] = sum_k (A[i,k]*w_r[k]) * B[j,k] + bias
// R3: split-bf16 GEMM via arch-neutral PTX (ldmatrix + mma.sync m16n8k16 bf16).
// Single GEMM with K'=1536: A'=[Ahi|Ahi|Alo], B'=[Bhi|Blo|Bhi]
//   => A'B'^T = Ahi*Bhi + Ahi*Blo + Alo*Bhi  (fp32 accum, rel err ~1e-5)
// tcgen05 is unusable: harness emits compute_103 PTX (no 'a' target).

#define DM_D   512
#define DM_KP  1536          // K' after split-concat
#define DM_N1  8192
#define DM_N2  8192
#define DM_BM  128
#define DM_BN  256
#define DM_BK  32            // bf16 elems per k-tile (64 bytes/row)
#define DM_KT  (DM_KP / DM_BK)   // 48 k-tiles
#define STAGES 3

// Split planes, row-major [N][1536] bf16.
__device__ __nv_bfloat16 g_A2[(size_t)DM_N1 * DM_KP];
__device__ __nv_bfloat16 g_B2[(size_t)DM_N2 * DM_KP];

// ---------------- PTX helpers ----------------
__device__ __forceinline__ uint32_t smem_u32(const void* p) {
    uint32_t a;
    asm("{ .reg .u64 t; cvta.to.shared.u64 t, %1; cvt.u32.u64 %0, t; }"
        : "=r"(a) : "l"(p));
    return a;
}

#define CP_ASYNC16(saddr, gptr) \
    asm volatile("cp.async.cg.shared.global [%0], [%1], 16;" :: "r"(saddr), "l"(gptr))
#define CP_COMMIT() asm volatile("cp.async.commit_group;" ::: "memory")
#define CP_WAIT(n)  asm volatile("cp.async.wait_group %0;" :: "n"(n) : "memory")

__device__ __forceinline__ void ldmx4(uint32_t* r, uint32_t addr) {
    asm volatile("ldmatrix.sync.aligned.m8n8.x4.shared.b16 {%0,%1,%2,%3}, [%4];"
                 : "=r"(r[0]), "=r"(r[1]), "=r"(r[2]), "=r"(r[3]) : "r"(addr));
}

__device__ __forceinline__ void mma16816(float* d, const uint32_t* a,
                                         uint32_t b0, uint32_t b1) {
    asm volatile(
        "mma.sync.aligned.m16n8k16.row.col.f32.bf16.bf16.f32 "
        "{%0,%1,%2,%3}, {%4,%5,%6,%7}, {%8,%9}, {%0,%1,%2,%3};"
        : "+f"(d[0]), "+f"(d[1]), "+f"(d[2]), "+f"(d[3])
        : "r"(a[0]), "r"(a[1]), "r"(a[2]), "r"(a[3]), "r"(b0), "r"(b1));
}

// ---------------- Pass 1: split conversion ----------------
__global__ __launch_bounds__(256)
void dm_convert_kernel(const float* __restrict__ A, const float* __restrict__ B,
                       const float* __restrict__ W, const int* __restrict__ tip) {
    const int idx = blockIdx.x * 256 + threadIdx.x;   // one float4 per thread
    const int r  = idx >> 7;                          // 128 groups per 512-row
    const int c4 = (idx & 127) * 4;
    const int ti = tip[0];

    const float4 w = *(const float4*)(W + (size_t)ti * DM_D + c4);
    const float4 a = *(const float4*)(A + (size_t)r * DM_D + c4);
    const float4 b = *(const float4*)(B + (size_t)r * DM_D + c4);

    float as[4] = {a.x * w.x, a.y * w.y, a.z * w.z, a.w * w.w};
    float bs[4] = {b.x, b.y, b.z, b.w};

    __nv_bfloat16 ah[4], al[4], bh[4], bl[4];
    #pragma unroll
    for (int i = 0; i < 4; i++) {
        ah[i] = __float2bfloat16_rn(as[i]);
        al[i] = __float2bfloat16_rn(as[i] - __bfloat162float(ah[i]));
        bh[i] = __float2bfloat16_rn(bs[i]);
        bl[i] = __float2bfloat16_rn(bs[i] - __bfloat162float(bh[i]));
    }

    __nv_bfloat16* arow = g_A2 + (size_t)r * DM_KP;
    __nv_bfloat16* brow = g_B2 + (size_t)r * DM_KP;
    // A' = [Ahi | Ahi | Alo]
    *(uint2*)(arow + c4)        = *(uint2*)ah;
    *(uint2*)(arow + 512 + c4)  = *(uint2*)ah;
    *(uint2*)(arow + 1024 + c4) = *(uint2*)al;
    // B' = [Bhi | Blo | Bhi]
    *(uint2*)(brow + c4)        = *(uint2*)bh;
    *(uint2*)(brow + 512 + c4)  = *(uint2*)bl;
    *(uint2*)(brow + 1024 + c4) = *(uint2*)bh;
}

// ---------------- Pass 2: GEMM ----------------
// smem: sA[STAGES][128 rows][64 B]  then sB[STAGES][256 rows][64 B]
// swizzle: 16B chunk c at row r stored at chunk (c ^ ((r>>1)&3))
#define STG_A 8192
#define STG_B 16384
#define SMEM_TOTAL (STAGES * (STG_A + STG_B))   // 73728

__global__ __launch_bounds__(256, 1)
void dm_gemm_kernel(const float* __restrict__ bias, float* __restrict__ C) {
    extern __shared__ char smem[];
    const uint32_t sbase = smem_u32(smem);
    const uint32_t sAb = sbase;
    const uint32_t sBb = sbase + STAGES * STG_A;

    const int tid  = threadIdx.x;
    const int wid  = tid >> 5;
    const int lane = tid & 31;
    const int warp_m = wid & 1;       // 2 warps over M (64 rows each)
    const int warp_n = wid >> 1;      // 4 warps over N (64 cols each)

    const int row0 = blockIdx.y * DM_BM;
    const int col0 = blockIdx.x * DM_BN;

    // --- global load mapping (16B chunks) ---
    // A tile: 128 rows x 4 chunks = 512 ; B tile: 256 rows x 4 = 1024
    const int ar[2] = {(tid * 2) >> 3, (tid * 2 + 1) >> 3};     // not used; see below

    // --- ldmatrix address precompute ---
    const int tile  = lane >> 3;
    const int lrow8 = lane & 7;
    // A: mat0=(m0-7,k0-7) mat1=(m8-15,k0-7) mat2=(m0-7,k8-15) mat3=(m8-15,k8-15)
    const int a_trow = (tile & 1) * 8;
    const int a_tcol = tile >> 1;
    uint32_t aByte[4]; int aMask[4];
    #pragma unroll
    for (int mi = 0; mi < 4; mi++) {
        int r = warp_m * 64 + mi * 16 + a_trow + lrow8;
        aByte[mi] = r * 64;
        aMask[mi] = (r >> 1) & 3;
    }
    // B: mat0=(n0-7,k0-7) mat1=(n0-7,k8-15) mat2=(n8-15,k0-7) mat3=(n8-15,k8-15)
    const int b_trow = (tile >> 1) * 8;
    const int b_tcol = tile & 1;
    uint32_t bByte[4]; int bMask[4];
    #pragma unroll
    for (int ni = 0; ni < 4; ni++) {
        int r = warp_n * 64 + ni * 16 + b_trow + lrow8;
        bByte[ni] = r * 64;
        bMask[ni] = (r >> 1) & 3;
    }

    float acc[4][8][4];
    #pragma unroll
    for (int mi = 0; mi < 4; mi++)
        #pragma unroll
        for (int nf = 0; nf < 8; nf++)
            #pragma unroll
            for (int q = 0; q < 4; q++) acc[mi][nf][q] = 0.0f;

    // --- tile loader ---
    auto load_tile = [&](int kt, int s) {
        const int kb = kt * DM_BK;   // element offset in K'
        // A: 512 chunks, 2 per thread
        #pragma unroll
        for (int i = 0; i < 2; i++) {
            int idx = tid + i * 256;
            int r = idx >> 2, c = idx & 3;
            const __nv_bfloat16* g = g_A2 + (size_t)(row0 + r) * DM_KP + kb + c * 8;
            uint32_t sa = sAb + s * STG_A + r * 64 + ((c ^ ((r >> 1) & 3)) << 4);
            CP_ASYNC16(sa, g);
        }
        // B: 1024 chunks, 4 per thread
        #pragma unroll
        for (int i = 0; i < 4; i++) {
            int idx = tid + i * 256;
            int r = idx >> 2, c = idx & 3;
            const __nv_bfloat16* g = g_B2 + (size_t)(col0 + r) * DM_KP + kb + c * 8;
            uint32_t sb = sBb + s * STG_B + r * 64 + ((c ^ ((r >> 1) & 3)) << 4);
            CP_ASYNC16(sb, g);
        }
    };

    // --- prologue ---
    #pragma unroll
    for (int s = 0; s < STAGES - 1; s++) {
        load_tile(s, s);
        CP_COMMIT();
    }

    // --- mainloop ---
    for (int kt = 0; kt < DM_KT; kt++) {
        CP_WAIT(STAGES - 2);
        __syncthreads();

        if (kt + STAGES - 1 < DM_KT) {
            load_tile(kt + STAGES - 1, (kt + STAGES - 1) % STAGES);
            CP_COMMIT();
        }

        const int s = kt % STAGES;
        const uint32_t sa0 = sAb + s * STG_A;
        const uint32_t sb0 = sBb + s * STG_B;

        #pragma unroll
        for (int ks = 0; ks < 2; ks++) {
            uint32_t afr[4][4], bfr[4][4];
            #pragma unroll
            for (int mi = 0; mi < 4; mi++)
                ldmx4(afr[mi], sa0 + aByte[mi] +
                               (((ks * 2 + a_tcol) ^ aMask[mi]) << 4));
            #pragma unroll
            for (int ni = 0; ni < 4; ni++)
                ldmx4(bfr[ni], sb0 + bByte[ni] +
                               (((ks * 2 + b_tcol) ^ bMask[ni]) << 4));
            #pragma unroll
            for (int mi = 0; mi < 4; mi++)
                #pragma unroll
                for (int ni = 0; ni < 4; ni++) {
                    mma16816(acc[mi][ni * 2 + 0], afr[mi], bfr[ni][0], bfr[ni][1]);
                    mma16816(acc[mi][ni * 2 + 1], afr[mi], bfr[ni][2], bfr[ni][3]);
                }
        }
        __syncthreads();
    }

    // --- epilogue ---
    const float bv = bias[0];
    const int er = lane >> 2;          // 0..7
    const int ec = (lane & 3) * 2;     // 0,2,4,6
    #pragma unroll
    for (int mi = 0; mi < 4; mi++) {
        const int rgl = row0 + warp_m * 64 + mi * 16 + er;
        float* c0 = C + (size_t)rgl * DM_N2 + col0 + warp_n * 64 + ec;
        float* c1 = C + (size_t)(rgl + 8) * DM_N2 + col0 + warp_n * 64 + ec;
        #pragma unroll
        for (int nf = 0; nf < 8; nf++) {
            float2 v0 = {acc[mi][nf][0] + bv, acc[mi][nf][1] + bv};
            float2 v1 = {acc[mi][nf][2] + bv, acc[mi][nf][3] + bv};
            *(float2*)(c0 + nf * 8) = v0;
            *(float2*)(c1 + nf * 8) = v1;
        }
    }
}

// ---------------- launch ----------------
extern "C" void kernel_launch(void* const* d_in, const int* in_sizes, int n_in,
                              void* d_out, int out_size) {
    const float* input1     = (const float*)d_in[0];   // [8192, 512]
    const float* input2     = (const float*)d_in[1];   // [8192, 512]
    const float* weight     = (const float*)d_in[2];   // [64, 512]
    const float* bias       = (const float*)d_in[3];   // [1]
    const int*   type_index = (const int*)  d_in[4];   // [1]
    float*       out        = (float*)d_out;           // [8192, 8192]

    cudaFuncSetAttribute(dm_gemm_kernel,
                         cudaFuncAttributeMaxDynamicSharedMemorySize, SMEM_TOTAL);

    dm_convert_kernel<<<DM_N1 * DM_D / 4 / 256, 256>>>(
        input1, input2, weight, type_index);

    dim3 grid(DM_N2 / DM_BN, DM_N1 / DM_BM);
    dm_gemm_kernel<<<grid, 256, SMEM_TOTAL>>>(bias, out);
}